// round 1
// baseline (speedup 1.0000x reference)
#include <cuda_runtime.h>

#define BB 16
#define CC 9
#define LL 1024
#define DD 16
#define HH 8
#define DFF 256
#define NCLS 10
#define C1 64

// ---------------- scratch (device globals: no allocation allowed) ----------------
__device__ float g_h1[BB*C1*CC*LL];    // conv1 raw output [b][o][c][l]  (37.7 MB)
__device__ float g_h2[BB*LL*DD];       // conv2 raw output [b][l][d]
__device__ float g_xsrc[BB*LL*DD];     // post bn2+gelu    [b][l][d]
__device__ float g_q[BB*HH*LL*2];      // [bh][l][2], pre-scaled by 0.25*log2e
__device__ float g_k[BB*HH*LL*2];
__device__ float g_v[BB*HH*LL*2];
__device__ float g_o[BB*LL*DD];        // attention output [b][l][d]
__device__ float g_s1sum[C1], g_s1sq[C1];
__device__ float g_s2sum[DD], g_s2sq[DD];
__device__ float g_bn1s[C1], g_bn1t[C1];
__device__ float g_bn2s[DD], g_bn2t[DD];
__device__ float g_pool[BB*DD];

__device__ __forceinline__ float gelu(float x) {
    return 0.5f * x * (1.0f + erff(x * 0.70710678118654752f));
}

// ---------------- zero stats/pool ----------------
__global__ void k_zero() {
    int tid = threadIdx.x;
    if (tid < C1) { g_s1sum[tid] = 0.f; g_s1sq[tid] = 0.f; }
    if (tid < DD) { g_s2sum[tid] = 0.f; g_s2sq[tid] = 0.f; }
    if (tid < BB*DD) g_pool[tid] = 0.f;
}

// ---------------- conv1 + BN1 partial stats ----------------
// grid 1024 = (b,o); 256 thr; each thread does 9 groups of 4 consecutive l
__global__ void k_conv1(const float* __restrict__ x, const float* __restrict__ w,
                        const float* __restrict__ bias) {
    __shared__ float sred[16];
    int bx = blockIdx.x;
    int b = bx >> 6, o = bx & 63;
    float wr[8];
#pragma unroll
    for (int k = 0; k < 8; k++) wr[k] = __ldg(&w[o*8 + k]);
    float bo = __ldg(&bias[o]);
    float s = 0.f, sq = 0.f;
    for (int eq = threadIdx.x; eq < (CC*LL/4); eq += 256) {
        int c = eq >> 8;
        int l0 = (eq & 255) << 2;
        const float* xr = x + (b*CC + c)*LL;
        float xv[11];
#pragma unroll
        for (int j = 0; j < 11; j++) {
            int li = l0 - 3 + j;
            xv[j] = (li >= 0 && li < LL) ? __ldg(&xr[li]) : 0.f;
        }
        float out[4];
#pragma unroll
        for (int t = 0; t < 4; t++) {
            float a = bo;
#pragma unroll
            for (int k = 0; k < 8; k++) a = fmaf(wr[k], xv[t + k], a);
            out[t] = a; s += a; sq = fmaf(a, a, sq);
        }
        float4 o4 = make_float4(out[0], out[1], out[2], out[3]);
        *(float4*)&g_h1[((b*C1 + o)*CC + c)*LL + l0] = o4;
    }
    // block reduce (all threads reach here: loop count uniform = 9)
#pragma unroll
    for (int off = 16; off; off >>= 1) {
        s  += __shfl_down_sync(0xffffffffu, s, off);
        sq += __shfl_down_sync(0xffffffffu, sq, off);
    }
    int lane = threadIdx.x & 31, wid = threadIdx.x >> 5;
    if (!lane) { sred[wid] = s; sred[8 + wid] = sq; }
    __syncthreads();
    if (threadIdx.x == 0) {
        float ts = 0.f, tq = 0.f;
#pragma unroll
        for (int i = 0; i < 8; i++) { ts += sred[i]; tq += sred[8 + i]; }
        atomicAdd(&g_s1sum[o], ts); atomicAdd(&g_s1sq[o], tq);
    }
}

__global__ void k_fin1(const float* __restrict__ g, const float* __restrict__ bb) {
    int o = threadIdx.x;
    const float invN = 1.f / (float)(BB*CC*LL);
    float mean = g_s1sum[o] * invN;
    float var  = g_s1sq[o] * invN - mean*mean;
    float sc = __ldg(&g[o]) * rsqrtf(var + 1e-5f);
    g_bn1s[o] = sc;
    g_bn1t[o] = __ldg(&bb[o]) - mean * sc;
}

// ---------------- bn1+gelu (in smem) + conv2 + BN2 partial stats ----------------
// grid 1024 = b(16) x ltile(64, 16 l each); 256 thr
__global__ void k_conv2(const float* __restrict__ w2, const float* __restrict__ c2b) {
    __shared__ float sA[16*580];
    __shared__ float sS[128];
    __shared__ float sSum[DD], sSq[DD];
    int b  = blockIdx.x >> 6;
    int l0 = (blockIdx.x & 63) << 4;
    int tid = threadIdx.x;
    if (tid < 64) { sS[tid] = g_bn1s[tid]; sS[64 + tid] = g_bn1t[tid]; }
    if (tid < DD) { sSum[tid] = 0.f; sSq[tid] = 0.f; }
    __syncthreads();
    for (int e = tid; e < 576*16; e += 256) {
        int ic = e >> 4, l = e & 15;
        float v = g_h1[(b*576 + ic)*LL + l0 + l];
        int i = ic / 9;
        v = fmaf(v, sS[i], sS[64 + i]);
        sA[l*580 + ic] = gelu(v);
    }
    __syncthreads();
    int d = tid >> 4, l = tid & 15;
    float acc = __ldg(&c2b[d]);
    const float4* wr = (const float4*)(w2 + d*576);
    const float4* ar = (const float4*)(sA + l*580);
#pragma unroll 8
    for (int j = 0; j < 144; j++) {
        float4 w4 = __ldg(&wr[j]);
        float4 a4 = ar[j];
        acc = fmaf(w4.x, a4.x, acc); acc = fmaf(w4.y, a4.y, acc);
        acc = fmaf(w4.z, a4.z, acc); acc = fmaf(w4.w, a4.w, acc);
    }
    g_h2[((b << 10) + l0 + l)*DD + d] = acc;
    atomicAdd(&sSum[d], acc); atomicAdd(&sSq[d], acc*acc);
    __syncthreads();
    if (tid < DD) { atomicAdd(&g_s2sum[tid], sSum[tid]); atomicAdd(&g_s2sq[tid], sSq[tid]); }
}

__global__ void k_fin2(const float* __restrict__ g, const float* __restrict__ bb) {
    int d = threadIdx.x;
    const float invN = 1.f / (float)(BB*LL);
    float mean = g_s2sum[d] * invN;
    float var  = g_s2sq[d] * invN - mean*mean;
    float sc = __ldg(&g[d]) * rsqrtf(var + 1e-5f);
    g_bn2s[d] = sc;
    g_bn2t[d] = __ldg(&bb[d]) - mean * sc;
}

// ---------------- bn2+gelu + pos-enc + QKV projections ----------------
// grid 64 x 256 thr; one token per thread
__global__ void k_qkv(const float* __restrict__ wq, const float* __restrict__ wk,
                      const float* __restrict__ wv) {
    __shared__ float sq_[256], sk_[256], sv_[256], s2s[16], s2t[16];
    int tid = threadIdx.x;
    sq_[tid] = __ldg(&wq[tid]); sk_[tid] = __ldg(&wk[tid]); sv_[tid] = __ldg(&wv[tid]);
    if (tid < 16) { s2s[tid] = g_bn2s[tid]; s2t[tid] = g_bn2t[tid]; }
    __syncthreads();
    int t = blockIdx.x*256 + tid;
    int l = t & 1023, b = t >> 10;
    float xp[16];
    const float4* hr = (const float4*)&g_h2[t*DD];
    float4* xsr = (float4*)&g_xsrc[t*DD];
#pragma unroll
    for (int i = 0; i < 4; i++) {
        float4 h4 = hr[i];
        float vs[4] = {h4.x, h4.y, h4.z, h4.w};
#pragma unroll
        for (int j = 0; j < 4; j++) {
            int d = i*4 + j;
            float v = gelu(fmaf(vs[j], s2s[d], s2t[d]));
            vs[j] = v; xp[d] = v;
        }
        xsr[i] = make_float4(vs[0], vs[1], vs[2], vs[3]);
    }
    const float divc[8] = {1.f, 0.31622776601683794f, 0.1f, 0.031622776601683794f,
                           0.01f, 0.0031622776601683794f, 0.001f, 0.00031622776601683794f};
    float lf = (float)l;
#pragma unroll
    for (int j = 0; j < 8; j++) {
        float ang = lf * divc[j] * 0.015625f;
        float sv, cv; sincosf(ang, &sv, &cv);
        xp[2*j]   += sv;
        xp[2*j+1] += cv;
    }
    const float QS = 0.36067376022224085f;  // 0.25 * log2(e)
#pragma unroll
    for (int h = 0; h < 8; h++) {
        float q0=0,q1=0,k0=0,k1=0,v0=0,v1=0;
#pragma unroll
        for (int e = 0; e < 16; e++) {
            float xv = xp[e];
            q0 = fmaf(xv, sq_[e*16 + 2*h    ], q0);
            q1 = fmaf(xv, sq_[e*16 + 2*h + 1], q1);
            k0 = fmaf(xv, sk_[e*16 + 2*h    ], k0);
            k1 = fmaf(xv, sk_[e*16 + 2*h + 1], k1);
            v0 = fmaf(xv, sv_[e*16 + 2*h    ], v0);
            v1 = fmaf(xv, sv_[e*16 + 2*h + 1], v1);
        }
        int idx = (b*8 + h)*LL + l;
        ((float2*)g_q)[idx] = make_float2(q0*QS, q1*QS);
        ((float2*)g_k)[idx] = make_float2(k0, k1);
        ((float2*)g_v)[idx] = make_float2(v0, v1);
    }
}

// ---------------- attention: softmax(q.k/4)@V + bias@V ----------------
// grid 512 = (bh:128) x (qtile:4 of 256); 256 thr; one q-row per thread
__global__ void k_attn(const float* __restrict__ rel) {
    __shared__ float sk[2048], sv[2048], srel[1280], sred[16];
    int bx = blockIdx.x;
    int tile = bx & 3, bh = bx >> 2, h = bh & 7;
    int q0 = tile << 8;
    int tid = threadIdx.x;
    int base = bh << 11;  // float offset of this (b,h) slab
    float mk0 = 0.f, mk1 = 0.f;
#pragma unroll
    for (int i = tid; i < 512; i += 256) {
        float4 kk = __ldg((const float4*)&g_k[base + i*4]);
        *(float4*)&sk[i*4] = kk;
        mk0 = fmaxf(mk0, fmaxf(fabsf(kk.x), fabsf(kk.z)));
        mk1 = fmaxf(mk1, fmaxf(fabsf(kk.y), fabsf(kk.w)));
        float4 vv = __ldg((const float4*)&g_v[base + i*4]);
        *(float4*)&sv[i*4] = vv;
    }
    for (int i = tid; i < 1279; i += 256)
        srel[i] = __ldg(&rel[(q0 + i)*8 + h]);
#pragma unroll
    for (int off = 16; off; off >>= 1) {
        mk0 = fmaxf(mk0, __shfl_xor_sync(0xffffffffu, mk0, off));
        mk1 = fmaxf(mk1, __shfl_xor_sync(0xffffffffu, mk1, off));
    }
    if ((tid & 31) == 0) { sred[tid >> 5] = mk0; sred[8 + (tid >> 5)] = mk1; }
    __syncthreads();
    float K0 = sred[0], K1 = sred[8];
#pragma unroll
    for (int i = 1; i < 8; i++) { K0 = fmaxf(K0, sred[i]); K1 = fmaxf(K1, sred[8+i]); }

    float2 qq = ((const float2*)g_q)[(bh << 10) + q0 + tid];
    // safe softmax shift: upper bound on max score (shift cancels in acc/l)
    float m = fabsf(qq.x)*K0 + fabsf(qq.y)*K1;
    float lsum = 0.f, a0 = 0.f, a1 = 0.f, c0 = 0.f, c1 = 0.f;
    int roff = tid + 1023;
#pragma unroll 4
    for (int k = 0; k < 1024; k++) {
        float2 kk = *(const float2*)&sk[2*k];   // broadcast
        float2 vv = *(const float2*)&sv[2*k];   // broadcast
        float r = srel[roff - k];
        float s = fmaf(qq.y, kk.y, qq.x*kk.x) - m;
        float e; asm("ex2.approx.f32 %0, %1;" : "=f"(e) : "f"(s));
        lsum += e;
        a0 = fmaf(e, vv.x, a0); a1 = fmaf(e, vv.y, a1);
        c0 = fmaf(r, vv.x, c0); c1 = fmaf(r, vv.y, c1);
    }
    float inv = 1.f / lsum;
    int b = bh >> 3;
    float2 out = make_float2(fmaf(a0, inv, c0), fmaf(a1, inv, c1));
    *(float2*)&g_o[((b << 10) + q0 + tid)*DD + 2*h] = out;
}

// ---------------- LN_attn + residual + LN1 + FFN + residual + LN2 + pool ----------------
// grid 64 x 256 thr; one token per thread
__global__ void k_post(const float* __restrict__ w1, const float* __restrict__ b1,
                       const float* __restrict__ w2, const float* __restrict__ b2,
                       const float* __restrict__ lag, const float* __restrict__ lab,
                       const float* __restrict__ l1g, const float* __restrict__ l1b,
                       const float* __restrict__ l2g, const float* __restrict__ l2b) {
    __shared__ float sW1T[4096];  // [j][d]
    __shared__ float sW2[4096];   // [j][d]
    __shared__ float sB1[256], sPool[16], sLn[96];
    int tid = threadIdx.x;
    for (int i = tid; i < 4096; i += 256) {
        sW1T[(i & 255)*16 + (i >> 8)] = __ldg(&w1[i]);  // w1 is [d][j]
        sW2[i] = __ldg(&w2[i]);                          // w2 is [j][d]
    }
    sB1[tid] = __ldg(&b1[tid]);
    if (tid < 16) {
        sPool[tid] = 0.f;
        sLn[tid]      = __ldg(&lag[tid]); sLn[16 + tid] = __ldg(&lab[tid]);
        sLn[32 + tid] = __ldg(&l1g[tid]); sLn[48 + tid] = __ldg(&l1b[tid]);
        sLn[64 + tid] = __ldg(&l2g[tid]); sLn[80 + tid] = __ldg(&l2b[tid]);
    }
    __syncthreads();
    int t = blockIdx.x*256 + tid;
    float v[16], xs[16], att[16], acc[16];
    const float4* orow = (const float4*)&g_o[t*DD];
    const float4* xrow = (const float4*)&g_xsrc[t*DD];
#pragma unroll
    for (int i = 0; i < 4; i++) {
        float4 f = orow[i]; v[4*i]=f.x; v[4*i+1]=f.y; v[4*i+2]=f.z; v[4*i+3]=f.w;
        float4 g = xrow[i]; xs[4*i]=g.x; xs[4*i+1]=g.y; xs[4*i+2]=g.z; xs[4*i+3]=g.w;
    }
    // LN(o, ln_attn)
    float mean = 0.f, sq = 0.f;
#pragma unroll
    for (int d = 0; d < 16; d++) { mean += v[d]; sq = fmaf(v[d], v[d], sq); }
    mean *= 0.0625f;
    float rs = rsqrtf(sq*0.0625f - mean*mean + 1e-5f);
    // x1 = xs + LN(o); LN1
    float m2 = 0.f, q2 = 0.f;
#pragma unroll
    for (int d = 0; d < 16; d++) {
        float x1 = xs[d] + fmaf((v[d]-mean)*rs, sLn[d], sLn[16+d]);
        v[d] = x1; m2 += x1; q2 = fmaf(x1, x1, q2);
    }
    m2 *= 0.0625f;
    float rs2 = rsqrtf(q2*0.0625f - m2*m2 + 1e-5f);
#pragma unroll
    for (int d = 0; d < 16; d++)
        att[d] = fmaf((v[d]-m2)*rs2, sLn[32+d], sLn[48+d]);
    // FFN
#pragma unroll
    for (int d = 0; d < 16; d++) acc[d] = __ldg(&b2[d]);
#pragma unroll 2
    for (int j = 0; j < 256; j++) {
        const float4* w1r = (const float4*)&sW1T[j*16];
        float hv = sB1[j];
#pragma unroll
        for (int i = 0; i < 4; i++) {
            float4 w4 = w1r[i];
            hv = fmaf(att[4*i], w4.x, hv); hv = fmaf(att[4*i+1], w4.y, hv);
            hv = fmaf(att[4*i+2], w4.z, hv); hv = fmaf(att[4*i+3], w4.w, hv);
        }
        hv = fmaxf(hv, 0.f);
        const float4* w2r = (const float4*)&sW2[j*16];
#pragma unroll
        for (int i = 0; i < 4; i++) {
            float4 w4 = w2r[i];
            acc[4*i]   = fmaf(hv, w4.x, acc[4*i]);
            acc[4*i+1] = fmaf(hv, w4.y, acc[4*i+1]);
            acc[4*i+2] = fmaf(hv, w4.z, acc[4*i+2]);
            acc[4*i+3] = fmaf(hv, w4.w, acc[4*i+3]);
        }
    }
    // x2 = att + ffn; LN2; pool
    float m3 = 0.f, q3 = 0.f;
#pragma unroll
    for (int d = 0; d < 16; d++) {
        float x2 = att[d] + acc[d];
        v[d] = x2; m3 += x2; q3 = fmaf(x2, x2, q3);
    }
    m3 *= 0.0625f;
    float rs3 = rsqrtf(q3*0.0625f - m3*m3 + 1e-5f);
#pragma unroll
    for (int d = 0; d < 16; d++) {
        float fin = fmaf((v[d]-m3)*rs3, sLn[64+d], sLn[80+d]);
        atomicAdd(&sPool[d], fin);
    }
    __syncthreads();
    if (tid < 16) atomicAdd(&g_pool[(blockIdx.x >> 2)*16 + tid], sPool[tid]);
}

// ---------------- final: mean-pool scale + classifier ----------------
__global__ void k_final(const float* __restrict__ ow, const float* __restrict__ ob,
                        float* __restrict__ out) {
    int tid = threadIdx.x;
    if (tid < BB*NCLS) {
        int b = tid / NCLS, n = tid % NCLS;
        float acc = __ldg(&ob[n]);
#pragma unroll
        for (int d = 0; d < 16; d++)
            acc = fmaf(g_pool[b*16 + d] * 0.0009765625f, __ldg(&ow[d*NCLS + n]), acc);
        out[tid] = acc;
    }
}

// ---------------- launch ----------------
extern "C" void kernel_launch(void* const* d_in, const int* in_sizes, int n_in,
                              void* d_out, int out_size) {
    const float* x    = (const float*)d_in[0];
    const float* c1w  = (const float*)d_in[1];
    const float* c1b  = (const float*)d_in[2];
    const float* bn1g = (const float*)d_in[3];
    const float* bn1b = (const float*)d_in[4];
    const float* c2w  = (const float*)d_in[5];
    const float* c2b  = (const float*)d_in[6];
    const float* bn2g = (const float*)d_in[7];
    const float* bn2b = (const float*)d_in[8];
    const float* wq   = (const float*)d_in[9];
    const float* wk   = (const float*)d_in[10];
    const float* wv   = (const float*)d_in[11];
    const float* rel  = (const float*)d_in[12];
    const float* lag  = (const float*)d_in[13];
    const float* lab  = (const float*)d_in[14];
    const float* l1g  = (const float*)d_in[15];
    const float* l1b  = (const float*)d_in[16];
    const float* fw1  = (const float*)d_in[17];
    const float* fb1  = (const float*)d_in[18];
    const float* fw2  = (const float*)d_in[19];
    const float* fb2  = (const float*)d_in[20];
    const float* l2g  = (const float*)d_in[21];
    const float* l2b  = (const float*)d_in[22];
    const float* ow   = (const float*)d_in[23];
    const float* ob   = (const float*)d_in[24];

    k_zero <<<1, 256>>>();
    k_conv1<<<1024, 256>>>(x, c1w, c1b);
    k_fin1 <<<1, 64>>>(bn1g, bn1b);
    k_conv2<<<1024, 256>>>(c2w, c2b);
    k_fin2 <<<1, 16>>>(bn2g, bn2b);
    k_qkv  <<<64, 256>>>(wq, wk, wv);
    k_attn <<<512, 256>>>(rel);
    k_post <<<64, 256>>>(fw1, fb1, fw2, fb2, lag, lab, l1g, l1b, l2g, l2b);
    k_final<<<1, 192>>>(ow, ob, (float*)d_out);
}

// round 3
// speedup vs baseline: 1.1061x; 1.1061x over previous
#include <cuda_runtime.h>

#define BB 16
#define CC 9
#define LL 1024
#define DD 16
#define HH 8
#define NCLS 10

typedef unsigned long long u64;

// ---------------- scratch ----------------
__device__ float g_h2[BB*LL*DD];       // conv2 (bias-free) [b][l][d]
__device__ float g_xsrc[BB*LL*DD];     // post bn2+gelu     [b][l][d]
__device__ float g_q[BB*HH*LL*2];      // AoS float2 per (bh,l), pre-scaled 0.25*log2e
__device__ float g_k[BB*HH*LL*2];      // SoA: [bh][ kx[1024] | ky[1024] ]
__device__ float g_v[BB*HH*LL*2];      // SoA: [bh][ vx[1024] | vy[1024] ]
__device__ float g_vp[BB*HH*LL*2];     // AoS float2 per (bh,l)
__device__ float g_o[BB*LL*DD];        // bias@V then += softmax@V
__device__ float g_w2t[CC*DD*64];      // [c][d][i]
__device__ float g_s1sum[64], g_s1sq[64];
__device__ float g_s2sum[DD], g_s2sq[DD];
__device__ float g_bn1s[64], g_bn1t[64];
__device__ float g_bn2s[DD], g_bn2t[DD];
__device__ float g_pool[BB*DD];

__device__ __forceinline__ float gelu(float x) {
    return 0.5f * x * (1.0f + erff(x * 0.70710678118654752f));
}
__device__ __forceinline__ float ex2f(float x) {
    float e; asm("ex2.approx.f32 %0, %1;" : "=f"(e) : "f"(x)); return e;
}
__device__ __forceinline__ u64 pk2(float lo, float hi) {
    u64 r; asm("mov.b64 %0, {%1,%2};" : "=l"(r) : "f"(lo), "f"(hi)); return r;
}
__device__ __forceinline__ void upk2(u64 a, float& lo, float& hi) {
    asm("mov.b64 {%0,%1}, %2;" : "=f"(lo), "=f"(hi) : "l"(a));
}
__device__ __forceinline__ u64 fma2_(u64 a, u64 b, u64 c) {
    u64 d; asm("fma.rn.f32x2 %0, %1, %2, %3;" : "=l"(d) : "l"(a), "l"(b), "l"(c)); return d;
}
__device__ __forceinline__ u64 add2_(u64 a, u64 b) {
    u64 d; asm("add.rn.f32x2 %0, %1, %2;" : "=l"(d) : "l"(a), "l"(b)); return d;
}

// ---------------- zero stats/pool + transpose w2 ----------------
// grid 36 x 256
__global__ void k_pre(const float* __restrict__ w2) {
    int tid = threadIdx.x;
    if (blockIdx.x == 0) {
        if (tid < 64) { g_s1sum[tid] = 0.f; g_s1sq[tid] = 0.f; }
        if (tid < DD) { g_s2sum[tid] = 0.f; g_s2sq[tid] = 0.f; }
        g_pool[tid] = 0.f;
    }
    int e = blockIdx.x*256 + tid;   // 0..9215
    int c = e >> 10, r = e & 1023, d = r >> 6, i = r & 63;
    g_w2t[e] = __ldg(&w2[d*576 + i*9 + c]);
}

// ---------------- conv1 stats only (bias-free; BN cancels bias) ----------------
// grid 144 = (b,c); 256 thr = 64 o x 4 sub
__global__ void k_stats1(const float* __restrict__ x, const float* __restrict__ w1) {
    __shared__ float sXe[1032];
    int b = blockIdx.x / 9, c = blockIdx.x % 9;
    int tid = threadIdx.x;
    for (int j = tid; j < 1031; j += 256) {
        int l = j - 3;
        sXe[j] = (l >= 0 && l < LL) ? __ldg(&x[(b*CC + c)*LL + l]) : 0.f;
    }
    __syncthreads();
    int o = tid >> 2, sub = tid & 3;
    float w[8];
#pragma unroll
    for (int k = 0; k < 8; k++) w[k] = __ldg(&w1[o*8 + k]);
    float s = 0.f, sq = 0.f;
#pragma unroll 4
    for (int li = 0; li < 256; li++) {
        int l = sub + li*4;
        float a = 0.f;
#pragma unroll
        for (int k = 0; k < 8; k++) a = fmaf(w[k], sXe[l + k], a);
        s += a; sq = fmaf(a, a, sq);
    }
    s  += __shfl_down_sync(0xffffffffu, s, 2, 4);
    s  += __shfl_down_sync(0xffffffffu, s, 1, 4);
    sq += __shfl_down_sync(0xffffffffu, sq, 2, 4);
    sq += __shfl_down_sync(0xffffffffu, sq, 1, 4);
    if (sub == 0) { atomicAdd(&g_s1sum[o], s); atomicAdd(&g_s1sq[o], sq); }
}

__global__ void k_fin1(const float* __restrict__ g, const float* __restrict__ bb) {
    int o = threadIdx.x;
    const float invN = 1.f / (float)(BB*CC*LL);
    float mean = g_s1sum[o] * invN;
    float var  = g_s1sq[o] * invN - mean*mean;
    float sc = __ldg(&g[o]) * rsqrtf(var + 1e-5f);
    g_bn1s[o] = sc;
    g_bn1t[o] = __ldg(&bb[o]) - mean * sc;
}

// ---------------- fused conv1 -> bn1 -> gelu -> conv2 (+BN2 stats) ----------------
// grid 256 = b(16) x ltile(16 of 64); 256 thr
__global__ void k_fused(const float* __restrict__ x, const float* __restrict__ w1) {
    __shared__ float sX[CC*72];     // x[c][l0-3 .. l0+67]
    __shared__ float sW1[512];
    __shared__ float sS[128];
    __shared__ float sA[64*68];     // per-c activations [i][l]
    __shared__ float sW2c[1024];    // per-c w2 [d][i]
    int tid = threadIdx.x;
    int b  = blockIdx.x >> 4;
    int l0 = (blockIdx.x & 15) << 6;
    for (int e = tid; e < CC*72; e += 256) {
        int c = e / 72, j = e - c*72;
        int l = l0 - 3 + j;
        sX[e] = (l >= 0 && l < LL && j < 71) ? __ldg(&x[(b*CC + c)*LL + l]) : 0.f;
    }
    for (int e = tid; e < 512; e += 256) sW1[e] = __ldg(&w1[e]);
    if (tid < 64) { sS[tid] = g_bn1s[tid]; sS[64 + tid] = g_bn1t[tid]; }

    int d = tid >> 4, lg = tid & 15;
    float4 acc = make_float4(0.f, 0.f, 0.f, 0.f);
    for (int c = 0; c < CC; c++) {
        __syncthreads();
        *(float4*)&sW2c[tid*4] = *(const float4*)&g_w2t[c*1024 + tid*4];
        const float* sxc = &sX[c*72];
        for (int e = tid; e < 4096; e += 256) {
            int i = e >> 6, l = e & 63;
            float a = 0.f;
#pragma unroll
            for (int k = 0; k < 8; k++) a = fmaf(sW1[i*8 + k], sxc[l + k], a);
            a = fmaf(a, sS[i], sS[64 + i]);
            sA[i*68 + l] = gelu(a);
        }
        __syncthreads();
        const float4* wrow = (const float4*)&sW2c[d*64];
        const float* ab0 = &sA[lg*4];
#pragma unroll
        for (int j = 0; j < 16; j++) {
            float4 w4 = wrow[j];
            const float* ab = ab0 + j*4*68;
            float4 a0 = *(const float4*)(ab);
            float4 a1 = *(const float4*)(ab + 68);
            float4 a2 = *(const float4*)(ab + 136);
            float4 a3 = *(const float4*)(ab + 204);
            acc.x = fmaf(w4.x,a0.x, fmaf(w4.y,a1.x, fmaf(w4.z,a2.x, fmaf(w4.w,a3.x, acc.x))));
            acc.y = fmaf(w4.x,a0.y, fmaf(w4.y,a1.y, fmaf(w4.z,a2.y, fmaf(w4.w,a3.y, acc.y))));
            acc.z = fmaf(w4.x,a0.z, fmaf(w4.y,a1.z, fmaf(w4.z,a2.z, fmaf(w4.w,a3.z, acc.z))));
            acc.w = fmaf(w4.x,a0.w, fmaf(w4.y,a1.w, fmaf(w4.z,a2.w, fmaf(w4.w,a3.w, acc.w))));
        }
    }
    // BN2 stats
    float s  = acc.x + acc.y + acc.z + acc.w;
    float sq = acc.x*acc.x + acc.y*acc.y + acc.z*acc.z + acc.w*acc.w;
#pragma unroll
    for (int off = 8; off; off >>= 1) {
        s  += __shfl_down_sync(0xffffffffu, s, off, 16);
        sq += __shfl_down_sync(0xffffffffu, sq, off, 16);
    }
    if (lg == 0) { atomicAdd(&g_s2sum[d], s); atomicAdd(&g_s2sq[d], sq); }
    // transpose via smem for coalesced store
    __syncthreads();
    sA[(lg*4 + 0)*17 + d] = acc.x;
    sA[(lg*4 + 1)*17 + d] = acc.y;
    sA[(lg*4 + 2)*17 + d] = acc.z;
    sA[(lg*4 + 3)*17 + d] = acc.w;
    __syncthreads();
    for (int e = tid; e < 1024; e += 256) {
        int l = e >> 4, dd = e & 15;
        g_h2[(b*LL + l0 + l)*DD + dd] = sA[l*17 + dd];
    }
}

__global__ void k_fin2(const float* __restrict__ g, const float* __restrict__ bb) {
    int d = threadIdx.x;
    const float invN = 1.f / (float)(BB*LL);
    float mean = g_s2sum[d] * invN;
    float var  = g_s2sq[d] * invN - mean*mean;
    float sc = __ldg(&g[d]) * rsqrtf(var + 1e-5f);
    g_bn2s[d] = sc;
    g_bn2t[d] = __ldg(&bb[d]) - mean * sc;
}

// ---------------- bn2+gelu + pos-enc + QKV (SoA k/v outputs) ----------------
// grid 64 x 256; one token per thread
__global__ void k_qkv(const float* __restrict__ wq, const float* __restrict__ wk,
                      const float* __restrict__ wv) {
    __shared__ float sq_[256], sk_[256], sv_[256], s2s[16], s2t[16];
    int tid = threadIdx.x;
    sq_[tid] = __ldg(&wq[tid]); sk_[tid] = __ldg(&wk[tid]); sv_[tid] = __ldg(&wv[tid]);
    if (tid < 16) { s2s[tid] = g_bn2s[tid]; s2t[tid] = g_bn2t[tid]; }
    __syncthreads();
    int t = blockIdx.x*256 + tid;
    int l = t & 1023, b = t >> 10;
    float xp[16];
    const float4* hr = (const float4*)&g_h2[t*DD];
    float4* xsr = (float4*)&g_xsrc[t*DD];
#pragma unroll
    for (int i = 0; i < 4; i++) {
        float4 h4 = hr[i];
        float vs[4] = {h4.x, h4.y, h4.z, h4.w};
#pragma unroll
        for (int j = 0; j < 4; j++) {
            int d = i*4 + j;
            float v = gelu(fmaf(vs[j], s2s[d], s2t[d]));
            vs[j] = v; xp[d] = v;
        }
        xsr[i] = make_float4(vs[0], vs[1], vs[2], vs[3]);
    }
    const float divc[8] = {1.f, 0.31622776601683794f, 0.1f, 0.031622776601683794f,
                           0.01f, 0.0031622776601683794f, 0.001f, 0.00031622776601683794f};
    float lf = (float)l;
#pragma unroll
    for (int j = 0; j < 8; j++) {
        float ang = lf * divc[j] * 0.015625f;
        float sv, cv; sincosf(ang, &sv, &cv);
        xp[2*j]   += sv;
        xp[2*j+1] += cv;
    }
    const float QS = 0.36067376022224085f;  // 0.25 * log2(e)
#pragma unroll
    for (int h = 0; h < 8; h++) {
        float q0=0,q1=0,k0=0,k1=0,v0=0,v1=0;
#pragma unroll
        for (int e = 0; e < 16; e++) {
            float xv = xp[e];
            q0 = fmaf(xv, sq_[e*16 + 2*h    ], q0);
            q1 = fmaf(xv, sq_[e*16 + 2*h + 1], q1);
            k0 = fmaf(xv, sk_[e*16 + 2*h    ], k0);
            k1 = fmaf(xv, sk_[e*16 + 2*h + 1], k1);
            v0 = fmaf(xv, sv_[e*16 + 2*h    ], v0);
            v1 = fmaf(xv, sv_[e*16 + 2*h + 1], v1);
        }
        int bh = b*8 + h, base2 = bh*2048;
        g_k[base2 + l] = k0;  g_k[base2 + 1024 + l] = k1;
        g_v[base2 + l] = v0;  g_v[base2 + 1024 + l] = v1;
        ((float2*)g_vp)[bh*1024 + l] = make_float2(v0, v1);
        ((float2*)g_q)[bh*1024 + l] = make_float2(q0*QS, q1*QS);
    }
}

// ---------------- bias@V (Toeplitz FIR), writes g_o ----------------
// grid 128 = bh; 256 thr x 4 consecutive q
__global__ void k_bias(const float* __restrict__ rel) {
    __shared__ float sv2[2048];
    __shared__ float srel[2048];
    int bh = blockIdx.x, h = bh & 7, b = bh >> 3;
    int tid = threadIdx.x;
    for (int i = tid; i < 512; i += 256)
        *(float4*)&sv2[i*4] = ((const float4*)g_vp)[bh*512 + i];
    for (int i = tid; i < 2047; i += 256)
        srel[i + 1] = __ldg(&rel[i*8 + h]);
    if (tid == 0) srel[0] = 0.f;
    __syncthreads();
    int q0 = tid << 2;
    float rv0 = srel[q0+1024], rv1 = srel[q0+1025], rv2 = srel[q0+1026], rv3 = srel[q0+1027];
    u64 ac0 = 0, ac1 = 0, ac2 = 0, ac3 = 0;
    const float* sr = &srel[q0 + 1023];
#pragma unroll 4
    for (int k = 0; k < 1024; k++) {
        u64 v2 = *(const u64*)&sv2[2*k];
        ac0 = fma2_(pk2(rv0, rv0), v2, ac0);
        ac1 = fma2_(pk2(rv1, rv1), v2, ac1);
        ac2 = fma2_(pk2(rv2, rv2), v2, ac2);
        ac3 = fma2_(pk2(rv3, rv3), v2, ac3);
        rv3 = rv2; rv2 = rv1; rv1 = rv0; rv0 = sr[-k];
    }
    int ti = b*LL + q0;
    float o0, o1;
    upk2(ac0, o0, o1); *(float2*)&g_o[(ti+0)*DD + 2*h] = make_float2(o0, o1);
    upk2(ac1, o0, o1); *(float2*)&g_o[(ti+1)*DD + 2*h] = make_float2(o0, o1);
    upk2(ac2, o0, o1); *(float2*)&g_o[(ti+2)*DD + 2*h] = make_float2(o0, o1);
    upk2(ac3, o0, o1); *(float2*)&g_o[(ti+3)*DD + 2*h] = make_float2(o0, o1);
}

// ---------------- attention: g_o += softmax(q.k/4)@V ----------------
// grid 512 = bh(128) x qtile(4 of 256); 256 thr; one q per thread; f32x2 2-key packing
__global__ void k_attn() {
    __shared__ float sk[2048];   // kx | ky
    __shared__ float sv[2048];   // vx | vy
    __shared__ float sred[16];
    int bx = blockIdx.x;
    int tile = bx & 3, bh = bx >> 2, h = bh & 7, b = bh >> 3;
    int q0 = tile << 8;
    int tid = threadIdx.x;
    float4 kx4 = ((const float4*)g_k)[bh*512 + tid];
    *(float4*)&sk[tid*4] = kx4;
    float mk0 = fmaxf(fmaxf(fabsf(kx4.x), fabsf(kx4.y)), fmaxf(fabsf(kx4.z), fabsf(kx4.w)));
    float4 ky4 = ((const float4*)g_k)[bh*512 + 256 + tid];
    *(float4*)&sk[1024 + tid*4] = ky4;
    float mk1 = fmaxf(fmaxf(fabsf(ky4.x), fabsf(ky4.y)), fmaxf(fabsf(ky4.z), fabsf(ky4.w)));
    *(float4*)&sv[tid*4]        = ((const float4*)g_v)[bh*512 + tid];
    *(float4*)&sv[1024 + tid*4] = ((const float4*)g_v)[bh*512 + 256 + tid];
#pragma unroll
    for (int off = 16; off; off >>= 1) {
        mk0 = fmaxf(mk0, __shfl_xor_sync(0xffffffffu, mk0, off));
        mk1 = fmaxf(mk1, __shfl_xor_sync(0xffffffffu, mk1, off));
    }
    if ((tid & 31) == 0) { sred[tid >> 5] = mk0; sred[8 + (tid >> 5)] = mk1; }
    __syncthreads();
    float K0 = sred[0], K1 = sred[8];
#pragma unroll
    for (int i = 1; i < 8; i++) { K0 = fmaxf(K0, sred[i]); K1 = fmaxf(K1, sred[8+i]); }

    float2 qq = ((const float2*)g_q)[(bh << 10) + q0 + tid];
    float m = fabsf(qq.x)*K0 + fabsf(qq.y)*K1;   // upper bound; shift cancels in acc/l
    u64 qx2 = pk2(qq.x, qq.x), qy2 = pk2(qq.y, qq.y), negm2 = pk2(-m, -m);
    u64 l2v = 0, a0 = 0, a1 = 0;
#pragma unroll 4
    for (int kk = 0; kk < 512; kk++) {
        u64 kx2 = *(const u64*)&sk[2*kk];
        u64 ky2 = *(const u64*)&sk[1024 + 2*kk];
        u64 s2 = fma2_(qy2, ky2, fma2_(qx2, kx2, negm2));
        float s0, s1; upk2(s2, s0, s1);
        u64 e2 = pk2(ex2f(s0), ex2f(s1));
        l2v = add2_(l2v, e2);
        a0 = fma2_(e2, *(const u64*)&sv[2*kk], a0);
        a1 = fma2_(e2, *(const u64*)&sv[1024 + 2*kk], a1);
    }
    float p0, p1;
    upk2(l2v, p0, p1); float inv = 1.f / (p0 + p1);
    upk2(a0, p0, p1);  float A0 = p0 + p1;
    upk2(a1, p0, p1);  float A1 = p0 + p1;
    int ti = b*LL + q0 + tid;
    float2 prev = *(const float2*)&g_o[ti*DD + 2*h];
    *(float2*)&g_o[ti*DD + 2*h] =
        make_float2(fmaf(A0, inv, prev.x), fmaf(A1, inv, prev.y));
}

// ---------------- LN_attn + res + LN1 + FFN + res + LN2 + pool ----------------
// grid 64 x 256; one token per thread
__global__ void k_post(const float* __restrict__ w1, const float* __restrict__ b1,
                       const float* __restrict__ w2, const float* __restrict__ b2,
                       const float* __restrict__ lag, const float* __restrict__ lab,
                       const float* __restrict__ l1g, const float* __restrict__ l1b,
                       const float* __restrict__ l2g, const float* __restrict__ l2b) {
    __shared__ float sW1T[4096];  // [j][d]
    __shared__ float sW2[4096];   // [j][d]
    __shared__ float sB1[256], sPool[16], sLn[96];
    int tid = threadIdx.x;
    for (int i = tid; i < 4096; i += 256) {
        sW1T[(i & 255)*16 + (i >> 8)] = __ldg(&w1[i]);
        sW2[i] = __ldg(&w2[i]);
    }
    sB1[tid] = __ldg(&b1[tid]);
    if (tid < 16) {
        sPool[tid] = 0.f;
        sLn[tid]      = __ldg(&lag[tid]); sLn[16 + tid] = __ldg(&lab[tid]);
        sLn[32 + tid] = __ldg(&l1g[tid]); sLn[48 + tid] = __ldg(&l1b[tid]);
        sLn[64 + tid] = __ldg(&l2g[tid]); sLn[80 + tid] = __ldg(&l2b[tid]);
    }
    __syncthreads();
    int t = blockIdx.x*256 + tid;
    float v[16], xs[16], att[16], acc[16];
    const float4* orow = (const float4*)&g_o[t*DD];
    const float4* xrow = (const float4*)&g_xsrc[t*DD];
#pragma unroll
    for (int i = 0; i < 4; i++) {
        float4 f = orow[i]; v[4*i]=f.x; v[4*i+1]=f.y; v[4*i+2]=f.z; v[4*i+3]=f.w;
        float4 g = xrow[i]; xs[4*i]=g.x; xs[4*i+1]=g.y; xs[4*i+2]=g.z; xs[4*i+3]=g.w;
    }
    float mean = 0.f, sq = 0.f;
#pragma unroll
    for (int d = 0; d < 16; d++) { mean += v[d]; sq = fmaf(v[d], v[d], sq); }
    mean *= 0.0625f;
    float rs = rsqrtf(sq*0.0625f - mean*mean + 1e-5f);
    float m2 = 0.f, q2 = 0.f;
#pragma unroll
    for (int d = 0; d < 16; d++) {
        float x1 = xs[d] + fmaf((v[d]-mean)*rs, sLn[d], sLn[16+d]);
        v[d] = x1; m2 += x1; q2 = fmaf(x1, x1, q2);
    }
    m2 *= 0.0625f;
    float rs2 = rsqrtf(q2*0.0625f - m2*m2 + 1e-5f);
#pragma unroll
    for (int d = 0; d < 16; d++)
        att[d] = fmaf((v[d]-m2)*rs2, sLn[32+d], sLn[48+d]);
#pragma unroll
    for (int d = 0; d < 16; d++) acc[d] = __ldg(&b2[d]);
#pragma unroll 2
    for (int j = 0; j < 256; j++) {
        const float4* w1r = (const float4*)&sW1T[j*16];
        float hv = sB1[j];
#pragma unroll
        for (int i = 0; i < 4; i++) {
            float4 w4 = w1r[i];
            hv = fmaf(att[4*i], w4.x, hv); hv = fmaf(att[4*i+1], w4.y, hv);
            hv = fmaf(att[4*i+2], w4.z, hv); hv = fmaf(att[4*i+3], w4.w, hv);
        }
        hv = fmaxf(hv, 0.f);
        const float4* w2r = (const float4*)&sW2[j*16];
#pragma unroll
        for (int i = 0; i < 4; i++) {
            float4 w4 = w2r[i];
            acc[4*i]   = fmaf(hv, w4.x, acc[4*i]);
            acc[4*i+1] = fmaf(hv, w4.y, acc[4*i+1]);
            acc[4*i+2] = fmaf(hv, w4.z, acc[4*i+2]);
            acc[4*i+3] = fmaf(hv, w4.w, acc[4*i+3]);
        }
    }
    float m3 = 0.f, q3 = 0.f;
#pragma unroll
    for (int d = 0; d < 16; d++) {
        float x2 = att[d] + acc[d];
        v[d] = x2; m3 += x2; q3 = fmaf(x2, x2, q3);
    }
    m3 *= 0.0625f;
    float rs3 = rsqrtf(q3*0.0625f - m3*m3 + 1e-5f);
#pragma unroll
    for (int d = 0; d < 16; d++) {
        float fin = fmaf((v[d]-m3)*rs3, sLn[64+d], sLn[80+d]);
        atomicAdd(&sPool[d], fin);
    }
    __syncthreads();
    if (tid < 16) atomicAdd(&g_pool[(blockIdx.x >> 2)*16 + tid], sPool[tid]);
}

// ---------------- final: mean-pool scale + classifier ----------------
__global__ void k_final(const float* __restrict__ ow, const float* __restrict__ ob,
                        float* __restrict__ out) {
    int tid = threadIdx.x;
    if (tid < BB*NCLS) {
        int b = tid / NCLS, n = tid % NCLS;
        float acc = __ldg(&ob[n]);
#pragma unroll
        for (int d = 0; d < 16; d++)
            acc = fmaf(g_pool[b*16 + d] * 0.0009765625f, __ldg(&ow[d*NCLS + n]), acc);
        out[tid] = acc;
    }
}

// ---------------- launch ----------------
extern "C" void kernel_launch(void* const* d_in, const int* in_sizes, int n_in,
                              void* d_out, int out_size) {
    const float* x    = (const float*)d_in[0];
    const float* c1w  = (const float*)d_in[1];
    const float* bn1g = (const float*)d_in[3];
    const float* bn1b = (const float*)d_in[4];
    const float* c2w  = (const float*)d_in[5];
    const float* bn2g = (const float*)d_in[7];
    const float* bn2b = (const float*)d_in[8];
    const float* wq   = (const float*)d_in[9];
    const float* wk   = (const float*)d_in[10];
    const float* wv   = (const float*)d_in[11];
    const float* rel  = (const float*)d_in[12];
    const float* lag  = (const float*)d_in[13];
    const float* lab  = (const float*)d_in[14];
    const float* l1g  = (const float*)d_in[15];
    const float* l1b  = (const float*)d_in[16];
    const float* fw1  = (const float*)d_in[17];
    const float* fb1  = (const float*)d_in[18];
    const float* fw2  = (const float*)d_in[19];
    const float* fb2  = (const float*)d_in[20];
    const float* l2g  = (const float*)d_in[21];
    const float* l2b  = (const float*)d_in[22];
    const float* ow   = (const float*)d_in[23];
    const float* ob   = (const float*)d_in[24];

    k_pre   <<<36, 256>>>(c2w);
    k_stats1<<<144, 256>>>(x, c1w);
    k_fin1  <<<1, 64>>>(bn1g, bn1b);
    k_fused <<<256, 256>>>(x, c1w);
    k_fin2  <<<1, 16>>>(bn2g, bn2b);
    k_qkv   <<<64, 256>>>(wq, wk, wv);
    k_bias  <<<128, 256>>>(rel);
    k_attn  <<<512, 256>>>();
    k_post  <<<64, 256>>>(fw1, fb1, fw2, fb2, lag, lab, l1g, l1b, l2g, l2b);
    k_final <<<1, 192>>>(ow, ob, (float*)d_out);
}

// round 5
// speedup vs baseline: 1.1884x; 1.0744x over previous
#include <cuda_runtime.h>

#define BB 16
#define CC 9
#define LL 1024
#define DD 16
#define HH 8
#define NCLS 10

typedef unsigned long long u64;

// ---------------- scratch ----------------
__device__ float g_h2[BB*LL*DD];       // conv2 accum (bias-free) [b][l][d]
__device__ float g_xsrc[BB*LL*DD];     // post bn2+gelu [b][l][d]
__device__ float g_q[BB*HH*LL*2];      // float2 per (bh,l), pre-scaled 0.25*log2e
__device__ float g_kv[BB*HH*LL*4];     // float4 per (bh,l): kx,ky,vx,vy
__device__ float g_o[BB*LL*DD];        // bias@V (atomic) then += softmax@V
__device__ float g_w2t[CC*DD*64];      // [c][d][i]
__device__ float g_s1sum[64], g_s1sq[64];
__device__ float g_s2sum[DD], g_s2sq[DD];
__device__ float g_bn1s[64], g_bn1t[64];
__device__ float g_bn2s[DD], g_bn2t[DD];
__device__ float g_pool[BB*DD];

__device__ __forceinline__ float ex2f(float x) {
    float e; asm("ex2.approx.f32 %0, %1;" : "=f"(e) : "f"(x)); return e;
}
// branch-free gelu via A&S 7.1.26 erf (|err| <= 1.5e-7)
__device__ __forceinline__ float gelu(float x) {
    float z = fabsf(x) * 0.70710678118654752f;
    float t; asm("rcp.approx.f32 %0, %1;" : "=f"(t) : "f"(fmaf(0.3275911f, z, 1.0f)));
    float p = fmaf(t, 1.061405429f, -1.453152027f);
    p = fmaf(t, p, 1.421413741f);
    p = fmaf(t, p, -0.284496736f);
    p = fmaf(t, p, 0.254829592f);
    p = p * t;
    float e = ex2f(z * z * -1.4426950408889634f);
    float r = fmaf(-p, e, 1.0f);
    return fmaf(0.5f * fabsf(x), r, 0.5f * x);
}

// ---------------- pre: zero stats/pool/g_o/g_h2 + transpose w2 ----------------
// grid 548 x 256
__global__ void k_pre(const float* __restrict__ w2) {
    int tid = threadIdx.x, bx = blockIdx.x;
    if (bx == 0) {
        if (tid < 64) { g_s1sum[tid] = 0.f; g_s1sq[tid] = 0.f; }
        if (tid < DD) { g_s2sum[tid] = 0.f; g_s2sq[tid] = 0.f; }
        g_pool[tid] = 0.f;
    }
    if (bx < 36) {
        int e = bx*256 + tid;   // 0..9215
        int c = e >> 10, r = e & 1023, d = r >> 6, i = r & 63;
        g_w2t[e] = __ldg(&w2[d*576 + i*9 + c]);
    } else {
        int e = (bx - 36)*256 + tid;    // 0..131071 float4s
        float4 z = make_float4(0.f, 0.f, 0.f, 0.f);
        if (e < 65536) ((float4*)g_o)[e] = z;
        else           ((float4*)g_h2)[e - 65536] = z;
    }
}

// ---------------- conv1 stats (bias-free; BN cancels conv bias) ----------------
// grid 144 = (b,c); 256 thr = 64 o x 4 sub
__global__ void k_stats1(const float* __restrict__ x, const float* __restrict__ w1) {
    __shared__ float sXe[1032];
    int b = blockIdx.x / 9, c = blockIdx.x % 9;
    int tid = threadIdx.x;
    for (int j = tid; j < 1031; j += 256) {
        int l = j - 3;
        sXe[j] = (l >= 0 && l < LL) ? __ldg(&x[(b*CC + c)*LL + l]) : 0.f;
    }
    __syncthreads();
    int o = tid >> 2, sub = tid & 3;
    float w[8];
#pragma unroll
    for (int k = 0; k < 8; k++) w[k] = __ldg(&w1[o*8 + k]);
    float s = 0.f, sq = 0.f;
#pragma unroll 4
    for (int li = 0; li < 256; li++) {
        int l = sub + li*4;
        float a = 0.f;
#pragma unroll
        for (int k = 0; k < 8; k++) a = fmaf(w[k], sXe[l + k], a);
        s += a; sq = fmaf(a, a, sq);
    }
    s  += __shfl_down_sync(0xffffffffu, s, 2, 4);
    s  += __shfl_down_sync(0xffffffffu, s, 1, 4);
    sq += __shfl_down_sync(0xffffffffu, sq, 2, 4);
    sq += __shfl_down_sync(0xffffffffu, sq, 1, 4);
    if (sub == 0) { atomicAdd(&g_s1sum[o], s); atomicAdd(&g_s1sq[o], sq); }
}

__global__ void k_fin1(const float* __restrict__ g, const float* __restrict__ bb) {
    int o = threadIdx.x;
    const float invN = 1.f / (float)(BB*CC*LL);
    float mean = g_s1sum[o] * invN;
    float var  = g_s1sq[o] * invN - mean*mean;
    float sc = __ldg(&g[o]) * rsqrtf(var + 1e-5f);
    g_bn1s[o] = sc;
    g_bn1t[o] = __ldg(&bb[o]) - mean * sc;
}

// ---------------- fused conv1->bn1->gelu->conv2 (c-split x3, atomic accum) ----------------
// grid 768 = b(16) x lt(16) x cg(3); 256 thr
__global__ void k_fused(const float* __restrict__ x, const float* __restrict__ w1) {
    __shared__ float sX[3*72];
    __shared__ float sW1[512];
    __shared__ float sS[128];
    __shared__ float sA[64*68];
    __shared__ float sW2c[1024];
    int bx = blockIdx.x;
    int cg = bx % 3; int tmp = bx / 3; int lt = tmp & 15; int b = tmp >> 4;
    int l0 = lt << 6;
    int tid = threadIdx.x;
    for (int e = tid; e < 3*72; e += 256) {
        int cc = e / 72, j = e - cc*72;
        int l = l0 - 3 + j;
        sX[e] = (l >= 0 && l < LL && j < 71) ? __ldg(&x[(b*CC + cg*3 + cc)*LL + l]) : 0.f;
    }
    for (int e = tid; e < 512; e += 256) sW1[e] = __ldg(&w1[e]);
    if (tid < 64) { sS[tid] = g_bn1s[tid]; sS[64 + tid] = g_bn1t[tid]; }

    int d = tid >> 4, lg = tid & 15;
    float4 acc = make_float4(0.f, 0.f, 0.f, 0.f);
    for (int cc = 0; cc < 3; cc++) {
        int c = cg*3 + cc;
        __syncthreads();
        *(float4*)&sW2c[tid*4] = *(const float4*)&g_w2t[c*1024 + tid*4];
        const float* sxc = &sX[cc*72];
        for (int e = tid; e < 4096; e += 256) {
            int i = e >> 6, l = e & 63;
            float a = 0.f;
#pragma unroll
            for (int k = 0; k < 8; k++) a = fmaf(sW1[i*8 + k], sxc[l + k], a);
            a = fmaf(a, sS[i], sS[64 + i]);
            sA[i*68 + l] = gelu(a);
        }
        __syncthreads();
        const float4* wrow = (const float4*)&sW2c[d*64];
        const float* ab0 = &sA[lg*4];
#pragma unroll
        for (int j = 0; j < 16; j++) {
            float4 w4 = wrow[j];
            const float* ab = ab0 + j*4*68;
            float4 a0 = *(const float4*)(ab);
            float4 a1 = *(const float4*)(ab + 68);
            float4 a2 = *(const float4*)(ab + 136);
            float4 a3 = *(const float4*)(ab + 204);
            acc.x = fmaf(w4.x,a0.x, fmaf(w4.y,a1.x, fmaf(w4.z,a2.x, fmaf(w4.w,a3.x, acc.x))));
            acc.y = fmaf(w4.x,a0.y, fmaf(w4.y,a1.y, fmaf(w4.z,a2.y, fmaf(w4.w,a3.y, acc.y))));
            acc.z = fmaf(w4.x,a0.z, fmaf(w4.y,a1.z, fmaf(w4.z,a2.z, fmaf(w4.w,a3.z, acc.z))));
            acc.w = fmaf(w4.x,a0.w, fmaf(w4.y,a1.w, fmaf(w4.z,a2.w, fmaf(w4.w,a3.w, acc.w))));
        }
    }
    int baseo = (b*LL + l0 + lg*4)*DD + d;
    atomicAdd(&g_h2[baseo     ], acc.x);
    atomicAdd(&g_h2[baseo + 16], acc.y);
    atomicAdd(&g_h2[baseo + 32], acc.z);
    atomicAdd(&g_h2[baseo + 48], acc.w);
}

// ---------------- BN2 stats from completed g_h2 ----------------
// grid 64 x 256
__global__ void k_stats2() {
    __shared__ float sS[128], sQ[128];
    int tid = threadIdx.x;
    int gt = blockIdx.x*256 + tid;
    int d = gt & 15;
    int tbase = gt >> 4;             // 0..1023
    float s = 0.f, q = 0.f;
#pragma unroll
    for (int i = 0; i < 16; i++) {
        float v = g_h2[(tbase + i*1024)*DD + d];
        s += v; q = fmaf(v, v, q);
    }
    s += __shfl_down_sync(0xffffffffu, s, 16);
    q += __shfl_down_sync(0xffffffffu, q, 16);
    int lane = tid & 31, w = tid >> 5;
    if (lane < 16) { sS[w*16 + lane] = s; sQ[w*16 + lane] = q; }
    __syncthreads();
    if (tid < 16) {
        float ts = 0.f, tq = 0.f;
#pragma unroll
        for (int i = 0; i < 8; i++) { ts += sS[i*16 + tid]; tq += sQ[i*16 + tid]; }
        atomicAdd(&g_s2sum[tid], ts); atomicAdd(&g_s2sq[tid], tq);
    }
}

__global__ void k_fin2(const float* __restrict__ g, const float* __restrict__ bb) {
    int d = threadIdx.x;
    const float invN = 1.f / (float)(BB*LL);
    float mean = g_s2sum[d] * invN;
    float var  = g_s2sq[d] * invN - mean*mean;
    float sc = __ldg(&g[d]) * rsqrtf(var + 1e-5f);
    g_bn2s[d] = sc;
    g_bn2t[d] = __ldg(&bb[d]) - mean * sc;
}

// ---------------- bn2+gelu + pos-enc + QKV (packed kv output) ----------------
// grid 128 x 128; one token per thread
__global__ void k_qkv(const float* __restrict__ wq, const float* __restrict__ wk,
                      const float* __restrict__ wv) {
    __shared__ float sq_[256], sk_[256], sv_[256], s2s[16], s2t[16];
    int tid = threadIdx.x;
    for (int e = tid; e < 256; e += 128) {
        sq_[e] = __ldg(&wq[e]); sk_[e] = __ldg(&wk[e]); sv_[e] = __ldg(&wv[e]);
    }
    if (tid < 16) { s2s[tid] = g_bn2s[tid]; s2t[tid] = g_bn2t[tid]; }
    __syncthreads();
    int t = blockIdx.x*128 + tid;
    int l = t & 1023, b = t >> 10;
    float xp[16];
    const float4* hr = (const float4*)&g_h2[t*DD];
    float4* xsr = (float4*)&g_xsrc[t*DD];
#pragma unroll
    for (int i = 0; i < 4; i++) {
        float4 h4 = hr[i];
        float vs[4] = {h4.x, h4.y, h4.z, h4.w};
#pragma unroll
        for (int j = 0; j < 4; j++) {
            int d = i*4 + j;
            float v = gelu(fmaf(vs[j], s2s[d], s2t[d]));
            vs[j] = v; xp[d] = v;
        }
        xsr[i] = make_float4(vs[0], vs[1], vs[2], vs[3]);
    }
    const float divc[8] = {1.f, 0.31622776601683794f, 0.1f, 0.031622776601683794f,
                           0.01f, 0.0031622776601683794f, 0.001f, 0.00031622776601683794f};
    float lf = (float)l;
#pragma unroll
    for (int j = 0; j < 8; j++) {
        float ang = lf * divc[j] * 0.015625f;
        float sv, cv; __sincosf(ang, &sv, &cv);
        xp[2*j]   += sv;
        xp[2*j+1] += cv;
    }
    const float QS = 0.36067376022224085f;  // 0.25 * log2(e)
#pragma unroll
    for (int h = 0; h < 8; h++) {
        float q0=0,q1=0,k0=0,k1=0,v0=0,v1=0;
#pragma unroll
        for (int e = 0; e < 16; e++) {
            float xv = xp[e];
            q0 = fmaf(xv, sq_[e*16 + 2*h    ], q0);
            q1 = fmaf(xv, sq_[e*16 + 2*h + 1], q1);
            k0 = fmaf(xv, sk_[e*16 + 2*h    ], k0);
            k1 = fmaf(xv, sk_[e*16 + 2*h + 1], k1);
            v0 = fmaf(xv, sv_[e*16 + 2*h    ], v0);
            v1 = fmaf(xv, sv_[e*16 + 2*h + 1], v1);
        }
        int idx = (b*8 + h)*LL + l;
        ((float4*)g_kv)[idx] = make_float4(k0, k1, v0, v1);
        ((float2*)g_q)[idx]  = make_float2(q0*QS, q1*QS);
    }
}

// ---------------- bias@V (Toeplitz FIR, key-split x2), RED into g_o ----------------
// grid 256 = bh(128) x ks(2); 256 thr x 4 consecutive q
__global__ void k_bias(const float* __restrict__ rel) {
    __shared__ float sv2[1024];
    __shared__ float srel[2048];
    int bx = blockIdx.x;
    int ks = bx & 1, bh = bx >> 1, h = bh & 7, b = bh >> 3;
    int k0 = ks << 9;
    int tid = threadIdx.x;
    for (int i = tid; i < 512; i += 256) {
        float4 kv = ((const float4*)g_kv)[bh*1024 + k0 + i];
        *(float2*)&sv2[i*2] = make_float2(kv.z, kv.w);
    }
    for (int i = tid; i < 2047; i += 256)
        srel[i + 1] = __ldg(&rel[i*8 + h]);
    if (tid == 0) srel[0] = 0.f;
    __syncthreads();
    int q0 = tid << 2;
    int ib = q0 + 1024 - k0;
    float rv0 = srel[ib], rv1 = srel[ib+1], rv2 = srel[ib+2], rv3 = srel[ib+3];
    float a00=0,a01=0,a10=0,a11=0,a20=0,a21=0,a30=0,a31=0;
    const float* sr = &srel[q0 + 1023 - k0];
#pragma unroll 4
    for (int k = 0; k < 512; k++) {
        float vx = sv2[2*k], vy = sv2[2*k+1];
        a00 = fmaf(rv0, vx, a00); a01 = fmaf(rv0, vy, a01);
        a10 = fmaf(rv1, vx, a10); a11 = fmaf(rv1, vy, a11);
        a20 = fmaf(rv2, vx, a20); a21 = fmaf(rv2, vy, a21);
        a30 = fmaf(rv3, vx, a30); a31 = fmaf(rv3, vy, a31);
        rv3 = rv2; rv2 = rv1; rv1 = rv0; rv0 = sr[-k];
    }
    int ti = b*LL + q0;
    atomicAdd(&g_o[(ti+0)*DD + 2*h    ], a00); atomicAdd(&g_o[(ti+0)*DD + 2*h + 1], a01);
    atomicAdd(&g_o[(ti+1)*DD + 2*h    ], a10); atomicAdd(&g_o[(ti+1)*DD + 2*h + 1], a11);
    atomicAdd(&g_o[(ti+2)*DD + 2*h    ], a20); atomicAdd(&g_o[(ti+2)*DD + 2*h + 1], a21);
    atomicAdd(&g_o[(ti+3)*DD + 2*h    ], a30); atomicAdd(&g_o[(ti+3)*DD + 2*h + 1], a31);
}

// ---------------- attention: g_o += softmax(q.k/4)@V ----------------
// grid 512 = bh(128) x qtile(4 of 256); 256 thr; one q per thread
__global__ void k_attn() {
    __shared__ float4 skv[1024];
    __shared__ float sred[16];
    int bx = blockIdx.x;
    int tile = bx & 3, bh = bx >> 2, h = bh & 7, b = bh >> 3;
    int q0 = tile << 8;
    int tid = threadIdx.x;
    float mk0 = 0.f, mk1 = 0.f;
#pragma unroll
    for (int i = 0; i < 4; i++) {
        float4 kv = ((const float4*)g_kv)[bh*1024 + tid*4 + i];
        skv[tid*4 + i] = kv;
        mk0 = fmaxf(mk0, fabsf(kv.x));
        mk1 = fmaxf(mk1, fabsf(kv.y));
    }
#pragma unroll
    for (int off = 16; off; off >>= 1) {
        mk0 = fmaxf(mk0, __shfl_xor_sync(0xffffffffu, mk0, off));
        mk1 = fmaxf(mk1, __shfl_xor_sync(0xffffffffu, mk1, off));
    }
    if ((tid & 31) == 0) { sred[tid >> 5] = mk0; sred[8 + (tid >> 5)] = mk1; }
    __syncthreads();
    float K0 = sred[0], K1 = sred[8];
#pragma unroll
    for (int i = 1; i < 8; i++) { K0 = fmaxf(K0, sred[i]); K1 = fmaxf(K1, sred[8+i]); }

    float2 qq = ((const float2*)g_q)[(bh << 10) + q0 + tid];
    float m = fabsf(qq.x)*K0 + fabsf(qq.y)*K1;   // upper bound; shift cancels in acc/l
    float qx = qq.x, qy = qq.y, nm = -m;
    float lsum = 0.f, a0 = 0.f, a1 = 0.f;
#pragma unroll 8
    for (int k = 0; k < 1024; k++) {
        float4 kv = skv[k];                       // broadcast LDS.128
        float s = fmaf(qy, kv.y, fmaf(qx, kv.x, nm));
        float e = ex2f(s);
        lsum += e;
        a0 = fmaf(e, kv.z, a0);
        a1 = fmaf(e, kv.w, a1);
    }
    float inv = 1.f / lsum;
    int ti = b*LL + q0 + tid;
    float2 prev = *(const float2*)&g_o[ti*DD + 2*h];
    *(float2*)&g_o[ti*DD + 2*h] =
        make_float2(fmaf(a0, inv, prev.x), fmaf(a1, inv, prev.y));
}

// ---------------- LN_attn + res + LN1 + FFN(j-split x4) + res + LN2 + pool ----------------
// grid 256 x 256; 4 threads per token
__global__ void k_post(const float* __restrict__ w1, const float* __restrict__ b1,
                       const float* __restrict__ w2, const float* __restrict__ b2,
                       const float* __restrict__ lag, const float* __restrict__ lab,
                       const float* __restrict__ l1g, const float* __restrict__ l1b,
                       const float* __restrict__ l2g, const float* __restrict__ l2b) {
    __shared__ float sW1T[4096];  // [j][d]
    __shared__ float sW2[4096];   // [j][d]
    __shared__ float sB1[256], sPool[16], sLn[112];
    int tid = threadIdx.x;
    for (int i = tid; i < 4096; i += 256) {
        sW1T[(i & 255)*16 + (i >> 8)] = __ldg(&w1[i]);
        sW2[i] = __ldg(&w2[i]);
    }
    sB1[tid] = __ldg(&b1[tid]);
    if (tid < 16) {
        sPool[tid] = 0.f;
        sLn[tid]      = __ldg(&lag[tid]); sLn[16 + tid] = __ldg(&lab[tid]);
        sLn[32 + tid] = __ldg(&l1g[tid]); sLn[48 + tid] = __ldg(&l1b[tid]);
        sLn[64 + tid] = __ldg(&l2g[tid]); sLn[80 + tid] = __ldg(&l2b[tid]);
        sLn[96 + tid] = __ldg(&b2[tid]);
    }
    __syncthreads();
    int sub = tid & 3;
    int t = blockIdx.x*64 + (tid >> 2);
    float v[16], xs[16], att[16], acc[16];
    const float4* orow = (const float4*)&g_o[t*DD];
    const float4* xrow = (const float4*)&g_xsrc[t*DD];
#pragma unroll
    for (int i = 0; i < 4; i++) {
        float4 f = orow[i]; v[4*i]=f.x; v[4*i+1]=f.y; v[4*i+2]=f.z; v[4*i+3]=f.w;
        float4 g = xrow[i]; xs[4*i]=g.x; xs[4*i+1]=g.y; xs[4*i+2]=g.z; xs[4*i+3]=g.w;
    }
    float mean = 0.f, sq = 0.f;
#pragma unroll
    for (int d = 0; d < 16; d++) { mean += v[d]; sq = fmaf(v[d], v[d], sq); }
    mean *= 0.0625f;
    float rs = rsqrtf(sq*0.0625f - mean*mean + 1e-5f);
    float m2 = 0.f, q2 = 0.f;
#pragma unroll
    for (int d = 0; d < 16; d++) {
        float x1 = xs[d] + fmaf((v[d]-mean)*rs, sLn[d], sLn[16+d]);
        v[d] = x1; m2 += x1; q2 = fmaf(x1, x1, q2);
    }
    m2 *= 0.0625f;
    float rs2 = rsqrtf(q2*0.0625f - m2*m2 + 1e-5f);
#pragma unroll
    for (int d = 0; d < 16; d++)
        att[d] = fmaf((v[d]-m2)*rs2, sLn[32+d], sLn[48+d]);
#pragma unroll
    for (int d = 0; d < 16; d++) acc[d] = 0.f;
    int j0 = sub << 6;
#pragma unroll 2
    for (int jj = 0; jj < 64; jj++) {
        int j = j0 + jj;
        const float4* w1r = (const float4*)&sW1T[j*16];
        float hv = sB1[j];
#pragma unroll
        for (int i = 0; i < 4; i++) {
            float4 w4 = w1r[i];
            hv = fmaf(att[4*i], w4.x, hv); hv = fmaf(att[4*i+1], w4.y, hv);
            hv = fmaf(att[4*i+2], w4.z, hv); hv = fmaf(att[4*i+3], w4.w, hv);
        }
        hv = fmaxf(hv, 0.f);
        const float4* w2r = (const float4*)&sW2[j*16];
#pragma unroll
        for (int i = 0; i < 4; i++) {
            float4 w4 = w2r[i];
            acc[4*i]   = fmaf(hv, w4.x, acc[4*i]);
            acc[4*i+1] = fmaf(hv, w4.y, acc[4*i+1]);
            acc[4*i+2] = fmaf(hv, w4.z, acc[4*i+2]);
            acc[4*i+3] = fmaf(hv, w4.w, acc[4*i+3]);
        }
    }
    // reduce partial FFN output across the 4 sub-threads
#pragma unroll
    for (int d = 0; d < 16; d++) {
        acc[d] += __shfl_xor_sync(0xffffffffu, acc[d], 1);
        acc[d] += __shfl_xor_sync(0xffffffffu, acc[d], 2);
    }
    float m3 = 0.f, q3 = 0.f;
#pragma unroll
    for (int d = 0; d < 16; d++) {
        float x2 = att[d] + acc[d] + sLn[96+d];
        v[d] = x2; m3 += x2; q3 = fmaf(x2, x2, q3);
    }
    m3 *= 0.0625f;
    float rs3 = rsqrtf(q3*0.0625f - m3*m3 + 1e-5f);
    if (sub == 0) {
#pragma unroll
        for (int d = 0; d < 16; d++) {
            float fin = fmaf((v[d]-m3)*rs3, sLn[64+d], sLn[80+d]);
            atomicAdd(&sPool[d], fin);
        }
    }
    __syncthreads();
    if (tid < 16) atomicAdd(&g_pool[(blockIdx.x >> 4)*16 + tid], sPool[tid]);
}

// ---------------- final: mean-pool scale + classifier ----------------
__global__ void k_final(const float* __restrict__ ow, const float* __restrict__ ob,
                        float* __restrict__ out) {
    int tid = threadIdx.x;
    if (tid < BB*NCLS) {
        int b = tid / NCLS, n = tid % NCLS;
        float acc = __ldg(&ob[n]);
#pragma unroll
        for (int d = 0; d < 16; d++)
            acc = fmaf(g_pool[b*16 + d] * 0.0009765625f, __ldg(&ow[d*NCLS + n]), acc);
        out[tid] = acc;
    }
}

// ---------------- launch ----------------
extern "C" void kernel_launch(void* const* d_in, const int* in_sizes, int n_in,
                              void* d_out, int out_size) {
    const float* x    = (const float*)d_in[0];
    const float* c1w  = (const float*)d_in[1];
    const float* bn1g = (const float*)d_in[3];
    const float* bn1b = (const float*)d_in[4];
    const float* c2w  = (const float*)d_in[5];
    const float* bn2g = (const float*)d_in[7];
    const float* bn2b = (const float*)d_in[8];
    const float* wq   = (const float*)d_in[9];
    const float* wk   = (const float*)d_in[10];
    const float* wv   = (const float*)d_in[11];
    const float* rel  = (const float*)d_in[12];
    const float* lag  = (const float*)d_in[13];
    const float* lab  = (const float*)d_in[14];
    const float* l1g  = (const float*)d_in[15];
    const float* l1b  = (const float*)d_in[16];
    const float* fw1  = (const float*)d_in[17];
    const float* fb1  = (const float*)d_in[18];
    const float* fw2  = (const float*)d_in[19];
    const float* fb2  = (const float*)d_in[20];
    const float* l2g  = (const float*)d_in[21];
    const float* l2b  = (const float*)d_in[22];
    const float* ow   = (const float*)d_in[23];
    const float* ob   = (const float*)d_in[24];

    k_pre   <<<548, 256>>>(c2w);
    k_stats1<<<144, 256>>>(x, c1w);
    k_fin1  <<<1, 64>>>(bn1g, bn1b);
    k_fused <<<768, 256>>>(x, c1w);
    k_stats2<<<64, 256>>>();
    k_fin2  <<<1, 16>>>(bn2g, bn2b);
    k_qkv   <<<128, 128>>>(wq, wk, wv);
    k_bias  <<<256, 256>>>(rel);
    k_attn  <<<512, 256>>>();
    k_post  <<<256, 256>>>(fw1, fb1, fw2, fb2, lag, lab, l1g, l1b, l2g, l2b);
    k_final <<<1, 192>>>(ow, ob, (float*)d_out);
}

// round 7
// speedup vs baseline: 1.2432x; 1.0462x over previous
#include <cuda_runtime.h>

#define BB 16
#define CC 9
#define LL 1024
#define DD 16
#define HH 8
#define NCLS 10

typedef unsigned long long u64;

// ---------------- scratch ----------------
__device__ float g_h2[BB*LL*DD];       // conv2 accum (bias-free) [b][l][d]
__device__ float g_xsrc[BB*LL*DD];     // post bn2+gelu [b][l][d]
__device__ float g_q[BB*HH*LL*2];      // float2 per (bh,l), pre-scaled 0.25*log2e
__device__ float g_soa[BB*HH*LL*4];    // per bh: kx[1024]|ky[1024]|vx[1024]|vy[1024]
__device__ float g_o[BB*LL*DD];        // attention output (softmax@V/l + bias@V)
__device__ float g_w2t[CC*DD*64];      // [c][d][i]
__device__ float g_s1sum[64], g_s1sq[64];
__device__ float g_s2sum[DD], g_s2sq[DD];
__device__ float g_pool[BB*DD];

__device__ __forceinline__ float ex2f(float x) {
    float e; asm("ex2.approx.f32 %0, %1;" : "=f"(e) : "f"(x)); return e;
}
__device__ __forceinline__ u64 pk2(float lo, float hi) {
    u64 r; asm("mov.b64 %0, {%1,%2};" : "=l"(r) : "f"(lo), "f"(hi)); return r;
}
__device__ __forceinline__ void upk2(u64 a, float& lo, float& hi) {
    asm("mov.b64 {%0,%1}, %2;" : "=f"(lo), "=f"(hi) : "l"(a));
}
__device__ __forceinline__ u64 fma2_(u64 a, u64 b, u64 c) {
    u64 d; asm("fma.rn.f32x2 %0, %1, %2, %3;" : "=l"(d) : "l"(a), "l"(b), "l"(c)); return d;
}
__device__ __forceinline__ u64 add2_(u64 a, u64 b) {
    u64 d; asm("add.rn.f32x2 %0, %1, %2;" : "=l"(d) : "l"(a), "l"(b)); return d;
}
// branch-free gelu via A&S 7.1.26 erf (|err| <= 1.5e-7)
__device__ __forceinline__ float gelu(float x) {
    float z = fabsf(x) * 0.70710678118654752f;
    float t; asm("rcp.approx.f32 %0, %1;" : "=f"(t) : "f"(fmaf(0.3275911f, z, 1.0f)));
    float p = fmaf(t, 1.061405429f, -1.453152027f);
    p = fmaf(t, p, 1.421413741f);
    p = fmaf(t, p, -0.284496736f);
    p = fmaf(t, p, 0.254829592f);
    p = p * t;
    float e = ex2f(z * z * -1.4426950408889634f);
    float r = fmaf(-p, e, 1.0f);
    return fmaf(0.5f * fabsf(x), r, 0.5f * x);
}

// ---------------- zero all atomic accumulators ----------------
__global__ void k_zero() {
    int tid = threadIdx.x;
    if (tid < 64) { g_s1sum[tid] = 0.f; g_s1sq[tid] = 0.f; }
    if (tid < DD) { g_s2sum[tid] = 0.f; g_s2sq[tid] = 0.f; }
    g_pool[tid] = 0.f;
}

// ---------------- pre: conv1 stats + transpose w2 + zero g_h2 ----------------
// grid 308 = stats(144) | w2t(36) | zero h2(128)
__global__ void k_pre(const float* __restrict__ x, const float* __restrict__ w1,
                      const float* __restrict__ w2) {
    __shared__ float sXe[1032];
    int bx = blockIdx.x, tid = threadIdx.x;
    if (bx < 144) {
        int b = bx / 9, c = bx % 9;
        for (int j = tid; j < 1031; j += 256) {
            int l = j - 3;
            sXe[j] = (l >= 0 && l < LL) ? __ldg(&x[(b*CC + c)*LL + l]) : 0.f;
        }
        __syncthreads();
        int o = tid >> 2, sub = tid & 3;
        float w[8];
#pragma unroll
        for (int k = 0; k < 8; k++) w[k] = __ldg(&w1[o*8 + k]);
        float s = 0.f, sq = 0.f;
#pragma unroll 4
        for (int li = 0; li < 256; li++) {
            int l = sub + li*4;
            float a = 0.f;
#pragma unroll
            for (int k = 0; k < 8; k++) a = fmaf(w[k], sXe[l + k], a);
            s += a; sq = fmaf(a, a, sq);
        }
        s  += __shfl_down_sync(0xffffffffu, s, 2, 4);
        s  += __shfl_down_sync(0xffffffffu, s, 1, 4);
        sq += __shfl_down_sync(0xffffffffu, sq, 2, 4);
        sq += __shfl_down_sync(0xffffffffu, sq, 1, 4);
        if (sub == 0) { atomicAdd(&g_s1sum[o], s); atomicAdd(&g_s1sq[o], sq); }
    } else if (bx < 180) {
        int e = (bx - 144)*256 + tid;   // 0..9215
        int c = e >> 10, r = e & 1023, d = r >> 6, i = r & 63;
        g_w2t[e] = __ldg(&w2[d*576 + i*9 + c]);
    } else {
        int e = (bx - 180)*256 + tid;   // 0..32767
        float4 z = make_float4(0.f, 0.f, 0.f, 0.f);
        ((float4*)g_h2)[e] = z;
        ((float4*)g_h2)[e + 32768] = z;
    }
}

// ---------------- fused conv1->bn1->gelu->conv2 (c-split x9, atomic accum) ----------------
// grid 2304 = b(16) x lt(16) x c(9); 256 thr; fin1 recomputed per block
__global__ void k_fused(const float* __restrict__ x, const float* __restrict__ w1,
                        const float* __restrict__ bn1g, const float* __restrict__ bn1b) {
    __shared__ float sX[72];
    __shared__ float sW1[512];
    __shared__ float sS[64], sT[64];
    __shared__ float sA[64*68];
    __shared__ float sW2c[1024];
    int bx = blockIdx.x;
    int c = bx % 9; int tmp = bx / 9; int lt = tmp & 15; int b = tmp >> 4;
    int l0 = lt << 6;
    int tid = threadIdx.x;
    if (tid < 71) {
        int l = l0 - 3 + tid;
        sX[tid] = (l >= 0 && l < LL) ? __ldg(&x[(b*CC + c)*LL + l]) : 0.f;
    }
    for (int e = tid; e < 512; e += 256) sW1[e] = __ldg(&w1[e]);
    *(float4*)&sW2c[tid*4] = *(const float4*)&g_w2t[c*1024 + tid*4];
    if (tid < 64) {
        const float invN = 1.f / 147456.f;
        float mean = g_s1sum[tid] * invN;
        float var  = g_s1sq[tid] * invN - mean*mean;
        float sc = __ldg(&bn1g[tid]) * rsqrtf(var + 1e-5f);
        sS[tid] = sc;
        sT[tid] = __ldg(&bn1b[tid]) - mean * sc;
    }
    __syncthreads();
    // activation: l fixed per thread -> x window in registers
    int l = tid & 63;
    float xw[8];
#pragma unroll
    for (int k = 0; k < 8; k++) xw[k] = sX[l + k];
    int i0 = tid >> 6;
#pragma unroll
    for (int it = 0; it < 16; it++) {
        int i = i0 + it*4;
        float a = 0.f;
#pragma unroll
        for (int k = 0; k < 8; k++) a = fmaf(sW1[i*8 + k], xw[k], a);
        a = fmaf(a, sS[i], sT[i]);
        sA[i*68 + l] = gelu(a);
    }
    __syncthreads();
    // conv2 partial GEMM over this c's 64 inputs
    int d = tid >> 4, lg = tid & 15;
    float4 acc = make_float4(0.f, 0.f, 0.f, 0.f);
    const float4* wrow = (const float4*)&sW2c[d*64];
    const float* ab0 = &sA[lg*4];
#pragma unroll
    for (int j = 0; j < 16; j++) {
        float4 w4 = wrow[j];
        const float* ab = ab0 + j*4*68;
        float4 a0 = *(const float4*)(ab);
        float4 a1 = *(const float4*)(ab + 68);
        float4 a2 = *(const float4*)(ab + 136);
        float4 a3 = *(const float4*)(ab + 204);
        acc.x = fmaf(w4.x,a0.x, fmaf(w4.y,a1.x, fmaf(w4.z,a2.x, fmaf(w4.w,a3.x, acc.x))));
        acc.y = fmaf(w4.x,a0.y, fmaf(w4.y,a1.y, fmaf(w4.z,a2.y, fmaf(w4.w,a3.y, acc.y))));
        acc.z = fmaf(w4.x,a0.z, fmaf(w4.y,a1.z, fmaf(w4.z,a2.z, fmaf(w4.w,a3.z, acc.z))));
        acc.w = fmaf(w4.x,a0.w, fmaf(w4.y,a1.w, fmaf(w4.z,a2.w, fmaf(w4.w,a3.w, acc.w))));
    }
    int baseo = (b*LL + l0 + lg*4)*DD + d;
    atomicAdd(&g_h2[baseo     ], acc.x);
    atomicAdd(&g_h2[baseo + 16], acc.y);
    atomicAdd(&g_h2[baseo + 32], acc.z);
    atomicAdd(&g_h2[baseo + 48], acc.w);
}

// ---------------- BN2 stats from completed g_h2 ----------------
// grid 64 x 256
__global__ void k_stats2() {
    __shared__ float sS[128], sQ[128];
    int tid = threadIdx.x;
    int gt = blockIdx.x*256 + tid;
    int d = gt & 15;
    int tbase = gt >> 4;
    float s = 0.f, q = 0.f;
#pragma unroll
    for (int i = 0; i < 16; i++) {
        float v = g_h2[(tbase + i*1024)*DD + d];
        s += v; q = fmaf(v, v, q);
    }
    s += __shfl_down_sync(0xffffffffu, s, 16);
    q += __shfl_down_sync(0xffffffffu, q, 16);
    int lane = tid & 31, w = tid >> 5;
    if (lane < 16) { sS[w*16 + lane] = s; sQ[w*16 + lane] = q; }
    __syncthreads();
    if (tid < 16) {
        float ts = 0.f, tq = 0.f;
#pragma unroll
        for (int i = 0; i < 8; i++) { ts += sS[i*16 + tid]; tq += sQ[i*16 + tid]; }
        atomicAdd(&g_s2sum[tid], ts); atomicAdd(&g_s2sq[tid], tq);
    }
}

// ---------------- bn2(fin in-block)+gelu + pos-enc + QKV (SoA outputs) ----------------
// grid 128 x 128; one token per thread
__global__ void k_qkv(const float* __restrict__ wq, const float* __restrict__ wk,
                      const float* __restrict__ wv,
                      const float* __restrict__ bn2g, const float* __restrict__ bn2b) {
    __shared__ float sq_[256], sk_[256], sv_[256], s2s[16], s2t[16];
    int tid = threadIdx.x;
    for (int e = tid; e < 256; e += 128) {
        sq_[e] = __ldg(&wq[e]); sk_[e] = __ldg(&wk[e]); sv_[e] = __ldg(&wv[e]);
    }
    if (tid < 16) {
        const float invN = 1.f / 16384.f;
        float mean = g_s2sum[tid] * invN;
        float var  = g_s2sq[tid] * invN - mean*mean;
        float sc = __ldg(&bn2g[tid]) * rsqrtf(var + 1e-5f);
        s2s[tid] = sc;
        s2t[tid] = __ldg(&bn2b[tid]) - mean * sc;
    }
    __syncthreads();
    int t = blockIdx.x*128 + tid;
    int l = t & 1023, b = t >> 10;
    float xp[16];
    const float4* hr = (const float4*)&g_h2[t*DD];
    float4* xsr = (float4*)&g_xsrc[t*DD];
#pragma unroll
    for (int i = 0; i < 4; i++) {
        float4 h4 = hr[i];
        float vs[4] = {h4.x, h4.y, h4.z, h4.w};
#pragma unroll
        for (int j = 0; j < 4; j++) {
            int d = i*4 + j;
            float v = gelu(fmaf(vs[j], s2s[d], s2t[d]));
            vs[j] = v; xp[d] = v;
        }
        xsr[i] = make_float4(vs[0], vs[1], vs[2], vs[3]);
    }
    const float divc[8] = {1.f, 0.31622776601683794f, 0.1f, 0.031622776601683794f,
                           0.01f, 0.0031622776601683794f, 0.001f, 0.00031622776601683794f};
    float lf = (float)l;
#pragma unroll
    for (int j = 0; j < 8; j++) {
        float ang = lf * divc[j] * 0.015625f;
        float sv, cv; __sincosf(ang, &sv, &cv);
        xp[2*j]   += sv;
        xp[2*j+1] += cv;
    }
    const float QS = 0.36067376022224085f;  // 0.25 * log2(e)
#pragma unroll
    for (int h = 0; h < 8; h++) {
        float q0=0,q1=0,k0=0,k1=0,v0=0,v1=0;
#pragma unroll
        for (int e = 0; e < 16; e++) {
            float xv = xp[e];
            q0 = fmaf(xv, sq_[e*16 + 2*h    ], q0);
            q1 = fmaf(xv, sq_[e*16 + 2*h + 1], q1);
            k0 = fmaf(xv, sk_[e*16 + 2*h    ], k0);
            k1 = fmaf(xv, sk_[e*16 + 2*h + 1], k1);
            v0 = fmaf(xv, sv_[e*16 + 2*h    ], v0);
            v1 = fmaf(xv, sv_[e*16 + 2*h + 1], v1);
        }
        int bh = b*8 + h;
        float* sb = &g_soa[bh*4096];
        sb[l] = k0; sb[1024 + l] = k1; sb[2048 + l] = v0; sb[3072 + l] = v1;
        ((float2*)g_q)[bh*1024 + l] = make_float2(q0*QS, q1*QS);
    }
}

// ---------------- attention: softmax(q.k/4)@V + bias@V in ONE loop ----------------
// grid 512 = bh(128) x qtile(4 of 256); 256 thr; one q per thread; f32x2 2-key packing
__global__ void k_attn(const float* __restrict__ rel) {
    __shared__ float skx[1024], sky[1024], svx[1024], svy[1024];
    __shared__ float2 sr0[640], sr1[640];
    __shared__ float sred[16];
    int bx = blockIdx.x;
    int tile = bx & 3, bh = bx >> 2, h = bh & 7, b = bh >> 3;
    int q0 = tile << 8;
    int tid = threadIdx.x;
    const float4* base = (const float4*)&g_soa[bh*4096];
    float4 x4 = base[tid];
    *(float4*)&skx[tid*4] = x4;
    float mk0 = fmaxf(fmaxf(fabsf(x4.x), fabsf(x4.y)), fmaxf(fabsf(x4.z), fabsf(x4.w)));
    float4 y4 = base[256 + tid];
    *(float4*)&sky[tid*4] = y4;
    float mk1 = fmaxf(fmaxf(fabsf(y4.x), fabsf(y4.y)), fmaxf(fabsf(y4.z), fabsf(y4.w)));
    *(float4*)&svx[tid*4] = base[512 + tid];
    *(float4*)&svy[tid*4] = base[768 + tid];
    // rel pairs, parity-preswapped: srel[i] := rel[(q0+i)*8+h], i in [0,1279)
    // sr0[s] = (srel[2s+1], srel[2s]); sr1[s] = (srel[2s+2], srel[2s+1])
    for (int s = tid; s < 640; s += 256) {
        int i2 = 2*s;
        float r0 = (i2     < 1279) ? __ldg(&rel[(q0 + i2    )*8 + h]) : 0.f;
        float r1 = (i2 + 1 < 1279) ? __ldg(&rel[(q0 + i2 + 1)*8 + h]) : 0.f;
        float r2 = (i2 + 2 < 1279) ? __ldg(&rel[(q0 + i2 + 2)*8 + h]) : 0.f;
        sr0[s] = make_float2(r1, r0);
        sr1[s] = make_float2(r2, r1);
    }
#pragma unroll
    for (int off = 16; off; off >>= 1) {
        mk0 = fmaxf(mk0, __shfl_xor_sync(0xffffffffu, mk0, off));
        mk1 = fmaxf(mk1, __shfl_xor_sync(0xffffffffu, mk1, off));
    }
    if ((tid & 31) == 0) { sred[tid >> 5] = mk0; sred[8 + (tid >> 5)] = mk1; }
    __syncthreads();
    float K0 = sred[0], K1 = sred[8];
#pragma unroll
    for (int i = 1; i < 8; i++) { K0 = fmaxf(K0, sred[i]); K1 = fmaxf(K1, sred[8+i]); }

    float2 qq = ((const float2*)g_q)[(bh << 10) + q0 + tid];
    float m = fabsf(qq.x)*K0 + fabsf(qq.y)*K1;   // upper bound; shift cancels in acc/l
    u64 qx2 = pk2(qq.x, qq.x), qy2 = pk2(qq.y, qq.y), negm2 = pk2(-m, -m);
    u64 l2 = 0, a0 = 0, a1 = 0, c0 = 0, c1 = 0;
    int p = tid & 1;
    int roff = ((tid - p) >> 1) + 511;
    const float2* srp = p ? sr1 : sr0;
#pragma unroll 4
    for (int kk = 0; kk < 512; kk++) {
        u64 kx2 = *(const u64*)&skx[2*kk];
        u64 ky2 = *(const u64*)&sky[2*kk];
        u64 vx2 = *(const u64*)&svx[2*kk];
        u64 vy2 = *(const u64*)&svy[2*kk];
        u64 s2 = fma2_(qy2, ky2, fma2_(qx2, kx2, negm2));
        float s0, s1; upk2(s2, s0, s1);
        u64 e2 = pk2(ex2f(s0), ex2f(s1));
        l2 = add2_(l2, e2);
        a0 = fma2_(e2, vx2, a0);
        a1 = fma2_(e2, vy2, a1);
        u64 r2 = *(const u64*)&srp[roff - kk];
        c0 = fma2_(r2, vx2, c0);
        c1 = fma2_(r2, vy2, c1);
    }
    float p0, p1;
    upk2(l2, p0, p1); float inv = 1.f / (p0 + p1);
    upk2(a0, p0, p1); float A0 = p0 + p1;
    upk2(a1, p0, p1); float A1 = p0 + p1;
    upk2(c0, p0, p1); float C0 = p0 + p1;
    upk2(c1, p0, p1); float C1 = p0 + p1;
    int ti = b*LL + q0 + tid;
    *(float2*)&g_o[ti*DD + 2*h] =
        make_float2(fmaf(A0, inv, C0), fmaf(A1, inv, C1));
}

// ---------------- LN_attn + res + LN1 + FFN(j-split x4) + res + LN2 + pool ----------------
// grid 256 x 256; 4 threads per token
__global__ void k_post(const float* __restrict__ w1, const float* __restrict__ b1,
                       const float* __restrict__ w2, const float* __restrict__ b2,
                       const float* __restrict__ lag, const float* __restrict__ lab,
                       const float* __restrict__ l1g, const float* __restrict__ l1b,
                       const float* __restrict__ l2g, const float* __restrict__ l2b) {
    __shared__ float sW1T[4096];  // [j][d]
    __shared__ float sW2[4096];   // [j][d]
    __shared__ float sB1[256], sPool[16], sLn[112];
    int tid = threadIdx.x;
    for (int i = tid; i < 4096; i += 256) {
        sW1T[(i & 255)*16 + (i >> 8)] = __ldg(&w1[i]);
        sW2[i] = __ldg(&w2[i]);
    }
    sB1[tid] = __ldg(&b1[tid]);
    if (tid < 16) {
        sPool[tid] = 0.f;
        sLn[tid]      = __ldg(&lag[tid]); sLn[16 + tid] = __ldg(&lab[tid]);
        sLn[32 + tid] = __ldg(&l1g[tid]); sLn[48 + tid] = __ldg(&l1b[tid]);
        sLn[64 + tid] = __ldg(&l2g[tid]); sLn[80 + tid] = __ldg(&l2b[tid]);
        sLn[96 + tid] = __ldg(&b2[tid]);
    }
    __syncthreads();
    int sub = tid & 3;
    int t = blockIdx.x*64 + (tid >> 2);
    float v[16], xs[16], att[16], acc[16];
    const float4* orow = (const float4*)&g_o[t*DD];
    const float4* xrow = (const float4*)&g_xsrc[t*DD];
#pragma unroll
    for (int i = 0; i < 4; i++) {
        float4 f = orow[i]; v[4*i]=f.x; v[4*i+1]=f.y; v[4*i+2]=f.z; v[4*i+3]=f.w;
        float4 g = xrow[i]; xs[4*i]=g.x; xs[4*i+1]=g.y; xs[4*i+2]=g.z; xs[4*i+3]=g.w;
    }
    float mean = 0.f, sq = 0.f;
#pragma unroll
    for (int d = 0; d < 16; d++) { mean += v[d]; sq = fmaf(v[d], v[d], sq); }
    mean *= 0.0625f;
    float rs = rsqrtf(sq*0.0625f - mean*mean + 1e-5f);
    float m2 = 0.f, q2 = 0.f;
#pragma unroll
    for (int d = 0; d < 16; d++) {
        float x1 = xs[d] + fmaf((v[d]-mean)*rs, sLn[d], sLn[16+d]);
        v[d] = x1; m2 += x1; q2 = fmaf(x1, x1, q2);
    }
    m2 *= 0.0625f;
    float rs2 = rsqrtf(q2*0.0625f - m2*m2 + 1e-5f);
#pragma unroll
    for (int d = 0; d < 16; d++)
        att[d] = fmaf((v[d]-m2)*rs2, sLn[32+d], sLn[48+d]);
#pragma unroll
    for (int d = 0; d < 16; d++) acc[d] = 0.f;
    int j0 = sub << 6;
#pragma unroll 2
    for (int jj = 0; jj < 64; jj++) {
        int j = j0 + jj;
        const float4* w1r = (const float4*)&sW1T[j*16];
        float hv = sB1[j];
#pragma unroll
        for (int i = 0; i < 4; i++) {
            float4 w4 = w1r[i];
            hv = fmaf(att[4*i], w4.x, hv); hv = fmaf(att[4*i+1], w4.y, hv);
            hv = fmaf(att[4*i+2], w4.z, hv); hv = fmaf(att[4*i+3], w4.w, hv);
        }
        hv = fmaxf(hv, 0.f);
        const float4* w2r = (const float4*)&sW2[j*16];
#pragma unroll
        for (int i = 0; i < 4; i++) {
            float4 w4 = w2r[i];
            acc[4*i]   = fmaf(hv, w4.x, acc[4*i]);
            acc[4*i+1] = fmaf(hv, w4.y, acc[4*i+1]);
            acc[4*i+2] = fmaf(hv, w4.z, acc[4*i+2]);
            acc[4*i+3] = fmaf(hv, w4.w, acc[4*i+3]);
        }
    }
#pragma unroll
    for (int d = 0; d < 16; d++) {
        acc[d] += __shfl_xor_sync(0xffffffffu, acc[d], 1);
        acc[d] += __shfl_xor_sync(0xffffffffu, acc[d], 2);
    }
    float m3 = 0.f, q3 = 0.f;
#pragma unroll
    for (int d = 0; d < 16; d++) {
        float x2 = att[d] + acc[d] + sLn[96+d];
        v[d] = x2; m3 += x2; q3 = fmaf(x2, x2, q3);
    }
    m3 *= 0.0625f;
    float rs3 = rsqrtf(q3*0.0625f - m3*m3 + 1e-5f);
    if (sub == 0) {
#pragma unroll
        for (int d = 0; d < 16; d++) {
            float fin = fmaf((v[d]-m3)*rs3, sLn[64+d], sLn[80+d]);
            atomicAdd(&sPool[d], fin);
        }
    }
    __syncthreads();
    if (tid < 16) atomicAdd(&g_pool[(blockIdx.x >> 4)*16 + tid], sPool[tid]);
}

// ---------------- final: mean-pool scale + classifier ----------------
__global__ void k_final(const float* __restrict__ ow, const float* __restrict__ ob,
                        float* __restrict__ out) {
    int tid = threadIdx.x;
    if (tid < BB*NCLS) {
        int b = tid / NCLS, n = tid % NCLS;
        float acc = __ldg(&ob[n]);
#pragma unroll
        for (int d = 0; d < 16; d++)
            acc = fmaf(g_pool[b*16 + d] * 0.0009765625f, __ldg(&ow[d*NCLS + n]), acc);
        out[tid] = acc;
    }
}

// ---------------- launch ----------------
extern "C" void kernel_launch(void* const* d_in, const int* in_sizes, int n_in,
                              void* d_out, int out_size) {
    const float* x    = (const float*)d_in[0];
    const float* c1w  = (const float*)d_in[1];
    const float* bn1g = (const float*)d_in[3];
    const float* bn1b = (const float*)d_in[4];
    const float* c2w  = (const float*)d_in[5];
    const float* bn2g = (const float*)d_in[7];
    const float* bn2b = (const float*)d_in[8];
    const float* wq   = (const float*)d_in[9];
    const float* wk   = (const float*)d_in[10];
    const float* wv   = (const float*)d_in[11];
    const float* rel  = (const float*)d_in[12];
    const float* lag  = (const float*)d_in[13];
    const float* lab  = (const float*)d_in[14];
    const float* l1g  = (const float*)d_in[15];
    const float* l1b  = (const float*)d_in[16];
    const float* fw1  = (const float*)d_in[17];
    const float* fb1  = (const float*)d_in[18];
    const float* fw2  = (const float*)d_in[19];
    const float* fb2  = (const float*)d_in[20];
    const float* l2g  = (const float*)d_in[21];
    const float* l2b  = (const float*)d_in[22];
    const float* ow   = (const float*)d_in[23];
    const float* ob   = (const float*)d_in[24];

    k_zero  <<<1, 256>>>();
    k_pre   <<<308, 256>>>(x, c1w, c2w);
    k_fused <<<2304, 256>>>(x, c1w, bn1g, bn1b);
    k_stats2<<<64, 256>>>();
    k_qkv   <<<128, 128>>>(wq, wk, wv, bn2g, bn2b);
    k_attn  <<<512, 256>>>(rel);
    k_post  <<<256, 256>>>(fw1, fb1, fw2, fb2, lag, lab, l1g, l1b, l2g, l2b);
    k_final <<<1, 192>>>(ow, ob, (float*)d_out);
}